// round 14
// baseline (speedup 1.0000x reference)
#include <cuda_runtime.h>
#include <cuda_bf16.h>
#include <stdint.h>

// LengthRegulator: B=32, S=1024, E=256
//   cum = cumsum(duration, axis=1); mel_len = cum[:, -1]; max_mel = max(mel_len)
//   out[b, t, :] = x[b, idx(b,t), :]  (searchsorted-right), tail rows zero,
//   mask[b,t] = (t >= mel_len[b]).
// Output buffer: [ out (B*max_mel*E f32) | mask (B*max_mel f32) ] if has_mask.
//
// R12: async data path. Gather via cp.async (LDGSTS, global->smem, no regs,
// no per-load scoreboard wait), store via cp.async.bulk (TMA bulk store of the
// block's contiguous 64KB output window). SM issues ~copy-free.

#define BB 32
#define SS 1024
#define EE 256

#define NTHR  256
#define WPB   8            // warps per block
#define WIN   64           // output rows per block (64 x 1KB = 64KB stage)
#define RPW   (WIN / WPB)  // 8 rows per warp
#define EPT   4            // duration elements per thread (1024/256)
#define STAGE_BYTES (WIN * EE * 4)

__device__ __forceinline__ void cp16(uint32_t dst_smem, const void* src) {
    asm volatile("cp.async.cg.shared.global [%0], [%1], 16;"
                 :: "r"(dst_smem), "l"(src) : "memory");
}

__global__ __launch_bounds__(NTHR)
void lr_fused_kernel(const float* __restrict__ x,
                     const void* __restrict__ dur_raw,
                     float* __restrict__ out,
                     int max_mel, int has_mask) {
    extern __shared__ float4 stage[];        // WIN rows x 64 float4
    __shared__ int s_idx[WIN];
    __shared__ int s_warpsum[WPB];
    __shared__ int s_is64;

    const int b    = blockIdx.y;
    const int W0   = blockIdx.x * WIN;
    const int tid  = threadIdx.x;
    const int lane = tid & 31;
    const int wid  = tid >> 5;

    // ---- dtype detect: int64 LE => odd 32-bit words are zero high-halves.
    if (wid == 0) {
        const unsigned* w = (const unsigned*)dur_raw;
        unsigned acc = 0;
        #pragma unroll
        for (int k = 0; k < 4; ++k) acc |= w[2 * (lane * 4 + k) + 1];
        unsigned any = __any_sync(0xffffffffu, acc != 0u);
        if (lane == 0) s_is64 = any ? 0 : 1;
    }
    __syncthreads();

    // ---- load 4 durations / thread
    int d[EPT];
    if (s_is64) {
        const long long* p = (const long long*)dur_raw + (size_t)b * SS + tid * EPT;
        #pragma unroll
        for (int e = 0; e < EPT; ++e) d[e] = (int)p[e];
    } else {
        const int* p = (const int*)dur_raw + (size_t)b * SS + tid * EPT;
        #pragma unroll
        for (int e = 0; e < EPT; ++e) d[e] = p[e];
    }

    // ---- block inclusive scan of 1024 durations
    int pfx[EPT];
    pfx[0] = d[0];
    #pragma unroll
    for (int e = 1; e < EPT; ++e) pfx[e] = pfx[e - 1] + d[e];
    const int tot = pfx[EPT - 1];

    int sv = tot;
    #pragma unroll
    for (int o = 1; o < 32; o <<= 1) {
        int n = __shfl_up_sync(0xffffffffu, sv, o);
        if (lane >= o) sv += n;
    }
    if (lane == 31) s_warpsum[wid] = sv;
    __syncthreads();
    if (wid == 0) {
        int ws = (lane < WPB) ? s_warpsum[lane] : 0;
        #pragma unroll
        for (int o = 1; o < WPB; o <<= 1) {
            int n = __shfl_up_sync(0xffffffffu, ws, o);
            if (lane >= o) ws += n;
        }
        if (lane < WPB) s_warpsum[lane] = ws;
    }
    __syncthreads();

    const int thr_base = (sv - tot) + (wid > 0 ? s_warpsum[wid - 1] : 0);
    const int L = s_warpsum[WPB - 1];            // mel_len[b]

    // ---- scatter source index into window
    const int W1 = W0 + WIN;
    {
        int exc = thr_base;
        #pragma unroll
        for (int e = 0; e < EPT; ++e) {
            const int inc = thr_base + pfx[e];
            int lo = exc > W0 ? exc : W0;
            int hi = inc < W1 ? inc : W1;
            for (int t = lo; t < hi; ++t) s_idx[t - W0] = tid * EPT + e;
            exc = inc;
        }
    }
    __syncthreads();

    // ---- mask (tiny direct store)
    if (has_mask && tid < WIN) {
        const int t = W0 + tid;
        if (t < max_mel)
            out[(size_t)BB * max_mel * EE + (size_t)b * max_mel + t] =
                (t >= L) ? 1.0f : 0.0f;
    }

    // ---- gather into stage: warp w owns local rows [w*RPW, w*RPW+RPW)
    // cp.async for live rows (2 x 16B per lane per row), STS zeros for tail.
    const float* __restrict__ xb = x + (size_t)b * SS * EE;
    const uint32_t stage_u32 = (uint32_t)__cvta_generic_to_shared(stage);
    const float4 z = make_float4(0.f, 0.f, 0.f, 0.f);

    #pragma unroll
    for (int i = 0; i < RPW; ++i) {
        const int tl = wid * RPW + i;            // local row
        const int t  = W0 + tl;                  // global output row
        const uint32_t dst = stage_u32 + (uint32_t)(tl * 64 + lane) * 16u;
        if (t < L) {
            const float* src = xb + (size_t)s_idx[tl] * EE + lane * 4;
            cp16(dst,        src);
            cp16(dst + 512,  src + 128);         // lane+32 chunk (+512B smem, +128 floats)
        } else {                                 // t >= L  (covers t >= max_mel too)
            stage[tl * 64 + lane]      = z;
            stage[tl * 64 + lane + 32] = z;
        }
    }
    asm volatile("cp.async.commit_group;" ::: "memory");
    asm volatile("cp.async.wait_group 0;" ::: "memory");
    // make generic-proxy smem writes (STS zeros) visible to the async proxy
    asm volatile("fence.proxy.async.shared::cta;" ::: "memory");
    __syncthreads();

    // ---- single bulk TMA store of the whole window (contiguous, 1KB-aligned)
    if (tid == 0) {
        int rows = max_mel - W0;
        if (rows > WIN) rows = WIN;
        float* gdst = out + ((size_t)b * max_mel + W0) * EE;
        asm volatile(
            "cp.async.bulk.global.shared::cta.bulk_group [%0], [%1], %2;"
            :: "l"(gdst), "r"(stage_u32), "r"((unsigned)(rows * EE * 4))
            : "memory");
        asm volatile("cp.async.bulk.commit_group;" ::: "memory");
        asm volatile("cp.async.bulk.wait_group 0;" ::: "memory");
    }
}

// ---------------------------------------------------------------------------
extern "C" void kernel_launch(void* const* d_in, const int* in_sizes, int n_in,
                              void* d_out, int out_size) {
    (void)in_sizes; (void)n_in;
    const float* x   = (const float*)d_in[0];
    const void*  dur = d_in[1];
    float* out = (float*)d_out;

    int has_mask, max_mel;
    if (out_size % (BB * (EE + 1)) == 0) {
        has_mask = 1;
        max_mel  = out_size / (BB * (EE + 1));
    } else {
        has_mask = 0;
        max_mel  = out_size / (BB * EE);
    }

    cudaFuncSetAttribute(lr_fused_kernel,
                         cudaFuncAttributeMaxDynamicSharedMemorySize,
                         STAGE_BYTES);

    dim3 grid((max_mel + WIN - 1) / WIN, BB);
    lr_fused_kernel<<<grid, NTHR, STAGE_BYTES>>>(x, dur, out, max_mel, has_mask);
}

// round 15
// speedup vs baseline: 1.4848x; 1.4848x over previous
#include <cuda_runtime.h>
#include <cuda_bf16.h>
#include <stdint.h>

// LengthRegulator: B=32, S=1024, E=256
//   cum = cumsum(duration, axis=1); mel_len = cum[:, -1]; max_mel = max(mel_len)
//   out[b, t, :] = x[b, idx(b,t), :]  (searchsorted-right), tail rows zero,
//   mask[b,t] = (t >= mel_len[b]).
// Output buffer: [ out (B*max_mel*E f32) | mask (B*max_mel f32) ] if has_mask.
//
// R14: revert to direct-store design (R12-async regressed: 64KB stage ->
// occ 28%, serialized store drain). WIN=128 rows/block, 512 threads, copy in
// two RPW=4 phases per warp -> scan prologue amortized over 2x bytes with
// unchanged register footprint.

#define BB 32
#define SS 1024
#define EE 256

#define NTHR  512
#define WPB   16                 // warps per block
#define RPW   4                  // rows per warp per phase
#define NPH   2                  // copy phases
#define WIN   (WPB * RPW * NPH)  // 128 output rows per block
#define EPT   2                  // duration elements per thread (1024/512)

__global__ __launch_bounds__(NTHR)
void lr_fused_kernel(const float* __restrict__ x,
                     const void* __restrict__ dur_raw,
                     float* __restrict__ out,
                     int max_mel, int has_mask) {
    __shared__ int s_idx[WIN];      // source row per window position
    __shared__ int s_warpsum[WPB];
    __shared__ int s_is64;

    const int b    = blockIdx.y;
    const int W0   = blockIdx.x * WIN;
    const int tid  = threadIdx.x;
    const int lane = tid & 31;
    const int wid  = tid >> 5;

    // ---- dtype detect: int64 LE => odd 32-bit words are zero high-halves.
    // (dur values 0..7 => false-positive prob ~8^-128 over 128 words)
    if (wid == 0) {
        const unsigned* w = (const unsigned*)dur_raw;
        unsigned acc = 0;
        #pragma unroll
        for (int k = 0; k < 4; ++k) acc |= w[2 * (lane * 4 + k) + 1];
        unsigned any = __any_sync(0xffffffffu, acc != 0u);
        if (lane == 0) s_is64 = any ? 0 : 1;
    }
    __syncthreads();

    // ---- load 2 durations / thread for this batch
    int d[EPT];
    if (s_is64) {
        const long long* p = (const long long*)dur_raw + (size_t)b * SS + tid * EPT;
        #pragma unroll
        for (int e = 0; e < EPT; ++e) d[e] = (int)p[e];
    } else {
        const int* p = (const int*)dur_raw + (size_t)b * SS + tid * EPT;
        #pragma unroll
        for (int e = 0; e < EPT; ++e) d[e] = p[e];
    }

    // ---- block inclusive scan of 1024 durations
    int pfx[EPT];
    pfx[0] = d[0];
    #pragma unroll
    for (int e = 1; e < EPT; ++e) pfx[e] = pfx[e - 1] + d[e];
    const int tot = pfx[EPT - 1];

    int sv = tot;
    #pragma unroll
    for (int o = 1; o < 32; o <<= 1) {
        int n = __shfl_up_sync(0xffffffffu, sv, o);
        if (lane >= o) sv += n;
    }
    if (lane == 31) s_warpsum[wid] = sv;
    __syncthreads();
    if (wid == 0) {
        int ws = (lane < WPB) ? s_warpsum[lane] : 0;
        #pragma unroll
        for (int o = 1; o < WPB; o <<= 1) {
            int n = __shfl_up_sync(0xffffffffu, ws, o);
            if (lane >= o) ws += n;
        }
        if (lane < WPB) s_warpsum[lane] = ws;
    }
    __syncthreads();

    const int thr_base = (sv - tot) + (wid > 0 ? s_warpsum[wid - 1] : 0);
    const int L = s_warpsum[WPB - 1];            // mel_len[b]

    // ---- scatter: source elem EPT*tid+e covers [thr_base+pfx[e-1], +pfx[e])
    const int W1 = W0 + WIN;
    {
        int exc = thr_base;
        #pragma unroll
        for (int e = 0; e < EPT; ++e) {
            const int inc = thr_base + pfx[e];
            int lo = exc > W0 ? exc : W0;
            int hi = inc < W1 ? inc : W1;
            for (int t = lo; t < hi; ++t) s_idx[t - W0] = tid * EPT + e;
            exc = inc;
        }
    }
    __syncthreads();

    // ---- mask for this window (coalesced)
    if (has_mask && tid < WIN) {
        const int t = W0 + tid;
        if (t < max_mel)
            out[(size_t)BB * max_mel * EE + (size_t)b * max_mel + t] =
                (t >= L) ? 1.0f : 0.0f;
    }

    // ---- expand: 2 phases x 4 rows/warp; 8 independent 16B loads then
    // 8 streaming 16B stores per phase. Registers reused across phases.
    const float* __restrict__ xb = x + (size_t)b * SS * EE;
    const float4 z = make_float4(0.f, 0.f, 0.f, 0.f);

    #pragma unroll
    for (int ph = 0; ph < NPH; ++ph) {
        const int t0 = W0 + (ph * WPB + wid) * RPW;

        int s[RPW];
        #pragma unroll
        for (int i = 0; i < RPW; ++i) {
            const int t = t0 + i;
            s[i] = (t < L && t < max_mel) ? s_idx[t - W0] : -1;
        }

        float4 v[RPW][2];
        #pragma unroll
        for (int i = 0; i < RPW; ++i) {
            if (s[i] >= 0) {
                const float4* __restrict__ xr =
                    (const float4*)(xb + (size_t)s[i] * EE);
                v[i][0] = __ldg(&xr[lane]);
                v[i][1] = __ldg(&xr[lane + 32]);
            } else {
                v[i][0] = z; v[i][1] = z;
            }
        }

        float4* __restrict__ obase =
            (float4*)(out + ((size_t)b * max_mel + t0) * EE);
        #pragma unroll
        for (int i = 0; i < RPW; ++i) {
            if (t0 + i < max_mel) {
                __stcs(&obase[i * (EE / 4) + lane],      v[i][0]);
                __stcs(&obase[i * (EE / 4) + lane + 32], v[i][1]);
            }
        }
    }
}

// ---------------------------------------------------------------------------
extern "C" void kernel_launch(void* const* d_in, const int* in_sizes, int n_in,
                              void* d_out, int out_size) {
    (void)in_sizes; (void)n_in;
    const float* x   = (const float*)d_in[0];
    const void*  dur = d_in[1];
    float* out = (float*)d_out;

    // Derive max_mel / layout from out_size (fixed per run).
    int has_mask, max_mel;
    if (out_size % (BB * (EE + 1)) == 0) {
        has_mask = 1;
        max_mel  = out_size / (BB * (EE + 1));
    } else {
        has_mask = 0;
        max_mel  = out_size / (BB * EE);
    }

    dim3 grid((max_mel + WIN - 1) / WIN, BB);
    lr_fused_kernel<<<grid, NTHR>>>(x, dur, out, max_mel, has_mask);
}

// round 16
// speedup vs baseline: 1.5000x; 1.0102x over previous
#include <cuda_runtime.h>
#include <cuda_bf16.h>
#include <stdint.h>

// LengthRegulator: B=32, S=1024, E=256
//   cum = cumsum(duration, axis=1); mel_len = cum[:, -1]; max_mel = max(mel_len)
//   out[b, t, :] = x[b, idx(b,t), :]  (searchsorted-right), tail rows zero,
//   mask[b,t] = (t >= mel_len[b]).
// Output buffer: [ out (B*max_mel*E f32) | mask (B*max_mel f32) ] if has_mask.
//
// R15: same WIN=128 two-phase design as R14, but the phase loop is
// `#pragma unroll 1` — R14's regression was ptxas keeping both unrolled
// phases' register arrays live (regs 58, occ 40%). One phase's footprint
// (~regs 36) restores R8 occupancy while keeping the 2x prologue
// amortization that WIN=128 buys.

#define BB 32
#define SS 1024
#define EE 256

#define NTHR  512
#define WPB   16                 // warps per block
#define RPW   4                  // rows per warp per phase
#define NPH   2                  // copy phases (sequential, not unrolled)
#define WIN   (WPB * RPW * NPH)  // 128 output rows per block
#define EPT   2                  // duration elements per thread (1024/512)

__global__ __launch_bounds__(NTHR)
void lr_fused_kernel(const float* __restrict__ x,
                     const void* __restrict__ dur_raw,
                     float* __restrict__ out,
                     int max_mel, int has_mask) {
    __shared__ int s_idx[WIN];      // source row per window position
    __shared__ int s_warpsum[WPB];
    __shared__ int s_is64;

    const int b    = blockIdx.y;
    const int W0   = blockIdx.x * WIN;
    const int tid  = threadIdx.x;
    const int lane = tid & 31;
    const int wid  = tid >> 5;

    // ---- dtype detect: int64 LE => odd 32-bit words are zero high-halves.
    // (dur values 0..7 => false-positive prob ~8^-128 over 128 words)
    if (wid == 0) {
        const unsigned* w = (const unsigned*)dur_raw;
        unsigned acc = 0;
        #pragma unroll
        for (int k = 0; k < 4; ++k) acc |= w[2 * (lane * 4 + k) + 1];
        unsigned any = __any_sync(0xffffffffu, acc != 0u);
        if (lane == 0) s_is64 = any ? 0 : 1;
    }
    __syncthreads();

    // ---- load 2 durations / thread for this batch
    int d[EPT];
    if (s_is64) {
        const long long* p = (const long long*)dur_raw + (size_t)b * SS + tid * EPT;
        #pragma unroll
        for (int e = 0; e < EPT; ++e) d[e] = (int)p[e];
    } else {
        const int* p = (const int*)dur_raw + (size_t)b * SS + tid * EPT;
        #pragma unroll
        for (int e = 0; e < EPT; ++e) d[e] = p[e];
    }

    // ---- block inclusive scan of 1024 durations
    int pfx[EPT];
    pfx[0] = d[0];
    #pragma unroll
    for (int e = 1; e < EPT; ++e) pfx[e] = pfx[e - 1] + d[e];
    const int tot = pfx[EPT - 1];

    int sv = tot;
    #pragma unroll
    for (int o = 1; o < 32; o <<= 1) {
        int n = __shfl_up_sync(0xffffffffu, sv, o);
        if (lane >= o) sv += n;
    }
    if (lane == 31) s_warpsum[wid] = sv;
    __syncthreads();
    if (wid == 0) {
        int ws = (lane < WPB) ? s_warpsum[lane] : 0;
        #pragma unroll
        for (int o = 1; o < WPB; o <<= 1) {
            int n = __shfl_up_sync(0xffffffffu, ws, o);
            if (lane >= o) ws += n;
        }
        if (lane < WPB) s_warpsum[lane] = ws;
    }
    __syncthreads();

    const int thr_base = (sv - tot) + (wid > 0 ? s_warpsum[wid - 1] : 0);
    const int L = s_warpsum[WPB - 1];            // mel_len[b]

    // ---- scatter: source elem EPT*tid+e covers [thr_base+pfx[e-1], +pfx[e])
    const int W1 = W0 + WIN;
    {
        int exc = thr_base;
        #pragma unroll
        for (int e = 0; e < EPT; ++e) {
            const int inc = thr_base + pfx[e];
            int lo = exc > W0 ? exc : W0;
            int hi = inc < W1 ? inc : W1;
            for (int t = lo; t < hi; ++t) s_idx[t - W0] = tid * EPT + e;
            exc = inc;
        }
    }
    __syncthreads();

    // ---- mask for this window (coalesced)
    if (has_mask && tid < WIN) {
        const int t = W0 + tid;
        if (t < max_mel)
            out[(size_t)BB * max_mel * EE + (size_t)b * max_mel + t] =
                (t >= L) ? 1.0f : 0.0f;
    }

    // ---- expand: NPH sequential phases (NOT unrolled -> one phase of regs),
    // each phase: 4 rows/warp, 8 independent 16B loads -> 8 streaming stores.
    const float* __restrict__ xb = x + (size_t)b * SS * EE;
    const float4 z = make_float4(0.f, 0.f, 0.f, 0.f);
    const bool interior = (W1 <= max_mel);       // full window, skip store guards

    #pragma unroll 1
    for (int ph = 0; ph < NPH; ++ph) {
        const int t0 = W0 + (ph * WPB + wid) * RPW;

        int s[RPW];
        #pragma unroll
        for (int i = 0; i < RPW; ++i) {
            const int t = t0 + i;
            s[i] = (t < L && t < max_mel) ? s_idx[t - W0] : -1;
        }

        float4 v[RPW][2];
        #pragma unroll
        for (int i = 0; i < RPW; ++i) {
            if (s[i] >= 0) {
                const float4* __restrict__ xr =
                    (const float4*)(xb + (size_t)s[i] * EE);
                v[i][0] = __ldg(&xr[lane]);
                v[i][1] = __ldg(&xr[lane + 32]);
            } else {
                v[i][0] = z; v[i][1] = z;
            }
        }

        float4* __restrict__ obase =
            (float4*)(out + ((size_t)b * max_mel + t0) * EE);
        if (interior) {
            #pragma unroll
            for (int i = 0; i < RPW; ++i) {
                __stcs(&obase[i * (EE / 4) + lane],      v[i][0]);
                __stcs(&obase[i * (EE / 4) + lane + 32], v[i][1]);
            }
        } else {
            #pragma unroll
            for (int i = 0; i < RPW; ++i) {
                if (t0 + i < max_mel) {
                    __stcs(&obase[i * (EE / 4) + lane],      v[i][0]);
                    __stcs(&obase[i * (EE / 4) + lane + 32], v[i][1]);
                }
            }
        }
    }
}

// ---------------------------------------------------------------------------
extern "C" void kernel_launch(void* const* d_in, const int* in_sizes, int n_in,
                              void* d_out, int out_size) {
    (void)in_sizes; (void)n_in;
    const float* x   = (const float*)d_in[0];
    const void*  dur = d_in[1];
    float* out = (float*)d_out;

    // Derive max_mel / layout from out_size (fixed per run).
    int has_mask, max_mel;
    if (out_size % (BB * (EE + 1)) == 0) {
        has_mask = 1;
        max_mel  = out_size / (BB * (EE + 1));
    } else {
        has_mask = 0;
        max_mel  = out_size / (BB * EE);
    }

    dim3 grid((max_mel + WIN - 1) / WIN, BB);
    lr_fused_kernel<<<grid, NTHR>>>(x, dur, out, max_mel, has_mask);
}